// round 8
// baseline (speedup 1.0000x reference)
#include <cuda_runtime.h>
#include <math.h>
#include <stdint.h>

#define BB 32
#define NN 384
#define RR 16
#define THREADS 384
#define TILE_ROWS 16
#define ROW_CHUNKS (NN / TILE_ROWS)               // 24
#define ORDER_BLOCKS (BB * ROW_CHUNKS)            // 768
#define REL_BLOCKS ((BB * NN) / THREADS)          // 32
#define GRID (ORDER_BLOCKS + REL_BLOCKS)          // 800
#define NWARPS (THREADS / 32)                     // 12
#define TILE_BYTES (TILE_ROWS * NN * 4)           // 24576
#define HUGE_RO 0x3fffffff
#define LN2F 0.69314718055994531f

// Scratch (no alloc allowed) — per-block partials + completion counter.
__device__ double g_osum[ORDER_BLOCKS];
__device__ double g_ocnt[ORDER_BLOCKS];
__device__ double g_rsum[REL_BLOCKS];
__device__ double g_rcnt[REL_BLOCKS];
__device__ unsigned int g_done = 0;

__device__ __forceinline__ uint32_t smem_u32(const void* p) {
    return (uint32_t)__cvta_generic_to_shared(p);
}

__global__ __launch_bounds__(THREADS)
void fused_kernel(const float* __restrict__ logits,
                  const float* __restrict__ rl,
                  const int* __restrict__ ro,
                  const int* __restrict__ parent,
                  const int* __restrict__ relation,
                  const int* __restrict__ mask,
                  float* __restrict__ out, int out_size) {
    __shared__ __align__(16) float tile[TILE_ROWS * NN];   // 24 KB
    __shared__ int s_s[NN];                                // mask ? ro : HUGE
    __shared__ __align__(8) unsigned long long mbar;
    __shared__ double ws[NWARPS], wc[NWARPS], ws2[NWARPS], wc2[NWARPS];
    __shared__ bool is_last;

    const int t    = threadIdx.x;
    const int warp = t >> 5;
    const int lane = t & 31;

    double blk_s = 0.0, blk_c = 0.0;

    if (blockIdx.x >= REL_BLOCKS) {
        // ---------------- order BCE part ----------------
        const int ob = blockIdx.x - REL_BLOCKS;
        const int b  = ob / ROW_CHUNKS;
        const int i0 = (ob % ROW_CHUNKS) * TILE_ROWS;
        const int j  = t;

        const uint32_t mbar_a = smem_u32(&mbar);

        if (t == 0) {
            asm volatile("mbarrier.init.shared.b64 [%0], %1;"
                         :: "r"(mbar_a), "r"(1) : "memory");
        }
        // ro/mask LDG issued here — latency overlaps the bulk copy below.
        const int m_me  = mask[b * NN + j];
        const int ro_me = ro[b * NN + j];
        s_s[j] = m_me ? ro_me : HUGE_RO;
        __syncthreads();

        if (t == 0) {
            const float* src = logits + ((size_t)b * NN + i0) * NN;
            asm volatile(
                "mbarrier.arrive.expect_tx.shared.b64 _, [%0], %1;"
                :: "r"(mbar_a), "r"((uint32_t)TILE_BYTES) : "memory");
            asm volatile(
                "cp.async.bulk.shared::cluster.global.mbarrier::complete_tx::bytes "
                "[%0], [%1], %2, [%3];"
                :: "r"(smem_u32(tile)), "l"(src),
                   "r"((uint32_t)TILE_BYTES), "r"(mbar_a) : "memory");
        }

        const int  sj = s_s[j];
        const bool pj = (sj < HUGE_RO);

        // Wait for the tile (parity 0).
        {
            uint32_t done;
            asm volatile(
                "{\n\t.reg .pred p;\n\t"
                "mbarrier.try_wait.parity.shared.b64 p, [%1], 0;\n\t"
                "selp.b32 %0, 1, 0, p;\n\t}"
                : "=r"(done) : "r"(mbar_a) : "memory");
            while (!done) {
                asm volatile(
                    "{\n\t.reg .pred p;\n\t"
                    "mbarrier.try_wait.parity.shared.b64 p, [%1], 0;\n\t"
                    "selp.b32 %0, 1, 0, p;\n\t}"
                    : "=r"(done) : "r"(mbar_a) : "memory");
            }
        }

        float fsum_y = 0.0f;   // sum of max(y,0)
        float fsum_l = 0.0f;   // sum of log2(1+exp(-|x|))
        int   cnt    = 0;

        #pragma unroll
        for (int ii = 0; ii < TILE_ROWS; ii++) {
            const float x  = tile[ii * NN + j];
            const int   si = s_s[i0 + ii];
            const bool valid = pj && (si < HUGE_RO);
            // target t = (ro_i < ro_j); bce = softplus(t ? -x : x)
            const float y  = (si < sj) ? -x : x;
            const float ax = fabsf(x);
            const float e  = __expf(-ax);
            const float lg = __log2f(1.0f + e);
            const float my = fmaxf(y, 0.0f);
            if (valid) { fsum_y += my; fsum_l += lg; cnt++; }
        }

        // Remove the diagonal element (i == j) if it fell in this row chunk.
        if (pj && j >= i0 && j < i0 + TILE_ROWS) {
            const float x  = tile[(j - i0) * NN + j];
            const float ax = fabsf(x);
            const float e  = __expf(-ax);
            const float lg = __log2f(1.0f + e);
            const float my = fmaxf(x, 0.0f);          // si==sj -> y = x
            fsum_y -= my; fsum_l -= lg; cnt--;
        }

        blk_s = (double)(fsum_y + LN2F * fsum_l);
        blk_c = (double)cnt;
    } else {
        // ---------------- relation CE part ----------------
        const int idx = blockIdx.x * THREADS + t;
        const int b = idx / NN;
        const int i = idx - b * NN;
        const int p = parent[idx];
        int       r = relation[idx];
        float ce = 0.0f;
        int   v  = 0;
        if (mask[idx] != 0 && p >= 0 && p < NN && r >= 0) {
            r = min(r, RR - 1);
            const float4* row =
                (const float4*)(rl + (((size_t)b * NN + p) * NN + i) * RR);
            float4 v0 = __ldg(row + 0);
            float4 v1 = __ldg(row + 1);
            float4 v2 = __ldg(row + 2);
            float4 v3 = __ldg(row + 3);
            float vals[RR] = {v0.x,v0.y,v0.z,v0.w, v1.x,v1.y,v1.z,v1.w,
                              v2.x,v2.y,v2.z,v2.w, v3.x,v3.y,v3.z,v3.w};
            float m = vals[0];
            #pragma unroll
            for (int k = 1; k < RR; k++) m = fmaxf(m, vals[k]);
            float ssum = 0.0f;
            #pragma unroll
            for (int k = 0; k < RR; k++) ssum += __expf(vals[k] - m);
            ce = m + __logf(ssum) - vals[r];
            v = 1;
        }
        blk_s = (double)ce;
        blk_c = (double)v;
    }

    // ---------------- block reduction (both paths) ----------------
    #pragma unroll
    for (int off = 16; off > 0; off >>= 1) {
        blk_s += __shfl_down_sync(0xffffffffu, blk_s, off);
        blk_c += __shfl_down_sync(0xffffffffu, blk_c, off);
    }
    if (lane == 0) { ws[warp] = blk_s; wc[warp] = blk_c; }
    __syncthreads();
    if (t == 0) {
        double S = 0.0, C = 0.0;
        #pragma unroll
        for (int w = 0; w < NWARPS; w++) { S += ws[w]; C += wc[w]; }
        if (blockIdx.x >= REL_BLOCKS) {
            g_osum[blockIdx.x - REL_BLOCKS] = S;
            g_ocnt[blockIdx.x - REL_BLOCKS] = C;
        } else {
            g_rsum[blockIdx.x] = S;
            g_rcnt[blockIdx.x] = C;
        }
    }

    // ---------------- last-block finalize ----------------
    __threadfence();
    if (t == 0) {
        is_last = (atomicAdd(&g_done, 1u) == (unsigned)(GRID - 1));
    }
    __syncthreads();
    if (!is_last) return;

    double os = 0.0, oc = 0.0, rs = 0.0, rc = 0.0;
    for (int k = t; k < ORDER_BLOCKS; k += THREADS) {
        os += __ldcg(&g_osum[k]);
        oc += __ldcg(&g_ocnt[k]);
    }
    if (t < REL_BLOCKS) {
        rs = __ldcg(&g_rsum[t]);
        rc = __ldcg(&g_rcnt[t]);
    }
    #pragma unroll
    for (int off = 16; off > 0; off >>= 1) {
        os += __shfl_down_sync(0xffffffffu, os, off);
        oc += __shfl_down_sync(0xffffffffu, oc, off);
        rs += __shfl_down_sync(0xffffffffu, rs, off);
        rc += __shfl_down_sync(0xffffffffu, rc, off);
    }
    if (lane == 0) { ws[warp] = os; wc[warp] = oc; ws2[warp] = rs; wc2[warp] = rc; }
    __syncthreads();
    if (t == 0) {
        double OS = 0.0, OC = 0.0, RS = 0.0, RC = 0.0;
        #pragma unroll
        for (int w = 0; w < NWARPS; w++) {
            OS += ws[w]; OC += wc[w]; RS += ws2[w]; RC += wc2[w];
        }
        const double order_loss = OS / fmax(OC, 1.0);
        const double rel_loss   = RS / fmax(RC, 1.0);
        const double total = order_loss + 0.5 * rel_loss;
        out[0] = (float)total;
        if (out_size > 1) out[1] = (float)order_loss;
        if (out_size > 2) out[2] = (float)rel_loss;
        g_done = 0;   // reset for next graph replay
    }
}

extern "C" void kernel_launch(void* const* d_in, const int* in_sizes, int n_in,
                              void* d_out, int out_size) {
    const float* order_logits    = (const float*)d_in[0];
    const float* relation_logits = (const float*)d_in[1];
    const int*   reading_orders  = (const int*)d_in[2];
    const int*   parent_ids      = (const int*)d_in[3];
    const int*   relations       = (const int*)d_in[4];
    const int*   region_mask     = (const int*)d_in[5];
    float* out = (float*)d_out;

    fused_kernel<<<GRID, THREADS>>>(order_logits, relation_logits,
                                    reading_orders, parent_ids, relations,
                                    region_mask, out, out_size);
}

// round 9
// speedup vs baseline: 1.2150x; 1.2150x over previous
#include <cuda_runtime.h>
#include <math.h>

#define BB 32
#define NN 384
#define RR 16
#define THREADS 384
#define ROWS_PER_BLOCK 32
#define ROW_CHUNKS (NN / ROWS_PER_BLOCK)          // 12
#define ORDER_BLOCKS (BB * ROW_CHUNKS)            // 384
#define REL_BLOCKS ((BB * NN) / THREADS)          // 32
#define GRID (ORDER_BLOCKS + REL_BLOCKS)          // 416
#define NWARPS (THREADS / 32)                     // 12
#define HUGE_RO 0x3fffffff
#define LN2F 0.69314718055994531f

// Scratch (no alloc allowed) — per-block partials + completion counter.
__device__ double g_osum[ORDER_BLOCKS];
__device__ double g_ocnt[ORDER_BLOCKS];
__device__ double g_rsum[REL_BLOCKS];
__device__ double g_rcnt[REL_BLOCKS];
__device__ unsigned int g_done = 0;

__global__ __launch_bounds__(THREADS)
void fused_kernel(const float* __restrict__ logits,
                  const float* __restrict__ rl,
                  const int* __restrict__ ro,
                  const int* __restrict__ parent,
                  const int* __restrict__ relation,
                  const int* __restrict__ mask,
                  float* __restrict__ out, int out_size) {
    __shared__ __align__(8) int2 s2[NN];   // {ro-or-HUGE, mask as float bits}
    __shared__ double ws[NWARPS], wc[NWARPS], ws2[NWARPS], wc2[NWARPS];
    __shared__ bool is_last;

    const int t    = threadIdx.x;
    const int warp = t >> 5;
    const int lane = t & 31;

    double blk_s = 0.0, blk_c = 0.0;

    if (blockIdx.x >= REL_BLOCKS) {
        // ---------------- order BCE part ----------------
        const int ob = blockIdx.x - REL_BLOCKS;
        const int b  = ob / ROW_CHUNKS;
        const int i0 = (ob % ROW_CHUNKS) * ROWS_PER_BLOCK;
        const int j  = t;

        const int m_me  = mask[b * NN + j];
        const int ro_me = ro[b * NN + j];
        int2 pack;
        pack.x = m_me ? ro_me : HUGE_RO;
        pack.y = __float_as_int(m_me ? 1.0f : 0.0f);
        s2[j] = pack;
        // Barrier doubles as valid-row counter for this tile (free cnt).
        const int nv_tile = __syncthreads_count(
            (j >= i0 && j < i0 + ROWS_PER_BLOCK) ? m_me : 0);

        const int  sj = pack.x;
        const bool pj = (sj < HUGE_RO);

        const float* base = logits + ((size_t)b * NN + i0) * NN + j;

        float ysum = 0.0f;   // Σ mif·max(x,0)
        float lsum = 0.0f;   // Σ mif·log2(1+exp(-|x|))
        float xtsum = 0.0f;  // Σ x·[si<sj]  (sentinel makes validity implicit)

        #pragma unroll 8
        for (int ii = 0; ii < ROWS_PER_BLOCK; ii++) {
            const float x   = __ldg(base + (size_t)ii * NN);
            const int2  v2  = s2[i0 + ii];           // one LDS.64, broadcast
            const int   si  = v2.x;
            const float mif = __int_as_float(v2.y);  // 1.0 or 0.0
            const float my  = fmaxf(x, 0.0f);
            ysum = fmaf(mif, my, ysum);
            const float e   = __expf(-fabsf(x));
            const float lg  = __log2f(1.0f + e);
            lsum = fmaf(mif, lg, lsum);
            xtsum += (si < sj) ? x : 0.0f;
        }

        int cnt = 0;
        if (pj) {
            cnt = nv_tile;
            // Diagonal correction: row i == j processed iff m_j (it is, pj).
            if (j >= i0 && j < i0 + ROWS_PER_BLOCK) {
                const float x  = __ldg(logits + (((size_t)b * NN + j) * NN + j));
                ysum -= fmaxf(x, 0.0f);
                lsum -= __log2f(1.0f + __expf(-fabsf(x)));
                cnt--;                                // (t=0 on diag: xtsum untouched)
            }
            blk_s = (double)(ysum - xtsum + LN2F * lsum);
        }
        blk_c = (double)cnt;
    } else {
        // ---------------- relation CE part ----------------
        const int idx = blockIdx.x * THREADS + t;
        const int b = idx / NN;
        const int i = idx - b * NN;
        const int p = parent[idx];
        int       r = relation[idx];
        float ce = 0.0f;
        int   v  = 0;
        if (mask[idx] != 0 && p >= 0 && p < NN && r >= 0) {
            r = min(r, RR - 1);
            const float4* row =
                (const float4*)(rl + (((size_t)b * NN + p) * NN + i) * RR);
            float4 v0 = __ldg(row + 0);
            float4 v1 = __ldg(row + 1);
            float4 v2 = __ldg(row + 2);
            float4 v3 = __ldg(row + 3);
            float vals[RR] = {v0.x,v0.y,v0.z,v0.w, v1.x,v1.y,v1.z,v1.w,
                              v2.x,v2.y,v2.z,v2.w, v3.x,v3.y,v3.z,v3.w};
            float m = vals[0];
            #pragma unroll
            for (int k = 1; k < RR; k++) m = fmaxf(m, vals[k]);
            float ssum = 0.0f;
            #pragma unroll
            for (int k = 0; k < RR; k++) ssum += __expf(vals[k] - m);
            ce = m + __logf(ssum) - vals[r];
            v = 1;
        }
        blk_s = (double)ce;
        blk_c = (double)v;
    }

    // ---------------- block reduction (both paths) ----------------
    #pragma unroll
    for (int off = 16; off > 0; off >>= 1) {
        blk_s += __shfl_down_sync(0xffffffffu, blk_s, off);
        blk_c += __shfl_down_sync(0xffffffffu, blk_c, off);
    }
    if (lane == 0) { ws[warp] = blk_s; wc[warp] = blk_c; }
    __syncthreads();
    if (t == 0) {
        double S = 0.0, C = 0.0;
        #pragma unroll
        for (int w = 0; w < NWARPS; w++) { S += ws[w]; C += wc[w]; }
        if (blockIdx.x >= REL_BLOCKS) {
            g_osum[blockIdx.x - REL_BLOCKS] = S;
            g_ocnt[blockIdx.x - REL_BLOCKS] = C;
        } else {
            g_rsum[blockIdx.x] = S;
            g_rcnt[blockIdx.x] = C;
        }
    }

    // ---------------- last-block finalize ----------------
    __threadfence();
    if (t == 0) {
        is_last = (atomicAdd(&g_done, 1u) == (unsigned)(GRID - 1));
    }
    __syncthreads();
    if (!is_last) return;

    double os = 0.0, oc = 0.0, rs = 0.0, rc = 0.0;
    for (int k = t; k < ORDER_BLOCKS; k += THREADS) {
        os += __ldcg(&g_osum[k]);
        oc += __ldcg(&g_ocnt[k]);
    }
    if (t < REL_BLOCKS) {
        rs = __ldcg(&g_rsum[t]);
        rc = __ldcg(&g_rcnt[t]);
    }
    #pragma unroll
    for (int off = 16; off > 0; off >>= 1) {
        os += __shfl_down_sync(0xffffffffu, os, off);
        oc += __shfl_down_sync(0xffffffffu, oc, off);
        rs += __shfl_down_sync(0xffffffffu, rs, off);
        rc += __shfl_down_sync(0xffffffffu, rc, off);
    }
    if (lane == 0) { ws[warp] = os; wc[warp] = oc; ws2[warp] = rs; wc2[warp] = rc; }
    __syncthreads();
    if (t == 0) {
        double OS = 0.0, OC = 0.0, RS = 0.0, RC = 0.0;
        #pragma unroll
        for (int w = 0; w < NWARPS; w++) {
            OS += ws[w]; OC += wc[w]; RS += ws2[w]; RC += wc2[w];
        }
        const double order_loss = OS / fmax(OC, 1.0);
        const double rel_loss   = RS / fmax(RC, 1.0);
        const double total = order_loss + 0.5 * rel_loss;
        out[0] = (float)total;
        if (out_size > 1) out[1] = (float)order_loss;
        if (out_size > 2) out[2] = (float)rel_loss;
        g_done = 0;   // reset for next graph replay
    }
}

extern "C" void kernel_launch(void* const* d_in, const int* in_sizes, int n_in,
                              void* d_out, int out_size) {
    const float* order_logits    = (const float*)d_in[0];
    const float* relation_logits = (const float*)d_in[1];
    const int*   reading_orders  = (const int*)d_in[2];
    const int*   parent_ids      = (const int*)d_in[3];
    const int*   relations       = (const int*)d_in[4];
    const int*   region_mask     = (const int*)d_in[5];
    float* out = (float*)d_out;

    fused_kernel<<<GRID, THREADS>>>(order_logits, relation_logits,
                                    reading_orders, parent_ids, relations,
                                    region_mask, out, out_size);
}